// round 15
// baseline (speedup 1.0000x reference)
#include <cuda_runtime.h>
#include <cuda_bf16.h>
#include <cstdint>

#define S_LEN 512
#define BATCH 8
#define HEADS 8
#define DHEAD 64
#define INDIM 512
#define PH    322                 // 5*D + 2
#define PROJ  (HEADS * PH)        // 2576
#define MROWS (S_LEN * BATCH)     // 4096
#define OUTD  (HEADS * DHEAD)     // 512

#define NCHUNK 4
#define CS     (S_LEN / NCHUNK)   // 128
#define MCHUNK (CS * BATCH)       // 1024

typedef unsigned long long ull;

// ---- scratch (static device memory) ----
__device__ float          g_qkvb[MROWS * PROJ];
__device__ float          g_z[MROWS * OUTD];          // z_t from wscan
__device__ __nv_bfloat16  g_normed_hi[MROWS * INDIM];
__device__ __nv_bfloat16  g_normed_lo[MROWS * INDIM];
__device__ __nv_bfloat16  g_hs_hi[MROWS * OUTD];
__device__ __nv_bfloat16  g_hs_lo[MROWS * OUTD];
__device__ __nv_bfloat16  g_wslow_hi[PROJ * INDIM];
__device__ __nv_bfloat16  g_wslow_lo[PROJ * INDIM];
__device__ __nv_bfloat16  g_wout_hi[INDIM * OUTD];
__device__ __nv_bfloat16  g_wout_lo[INDIM * OUTD];
// scan state across chunks
__device__ ull   g_Wst[64 * 128 * 16];
__device__ ull   g_Rst[64 * 128 * 16];
__device__ float g_hst[64 * 64];

__device__ __forceinline__ void split_bf16(float x, __nv_bfloat16& hi, __nv_bfloat16& lo)
{
    hi = __float2bfloat16_rn(x);
    lo = __float2bfloat16_rn(x - __bfloat162float(hi));
}

__device__ __forceinline__ void mma_bf16(float* c, const uint32_t* a, const uint32_t* b)
{
    asm volatile(
        "mma.sync.aligned.m16n8k16.row.col.f32.bf16.bf16.f32 "
        "{%0,%1,%2,%3}, {%4,%5,%6,%7}, {%8,%9}, {%0,%1,%2,%3};"
        : "+f"(c[0]), "+f"(c[1]), "+f"(c[2]), "+f"(c[3])
        : "r"(a[0]), "r"(a[1]), "r"(a[2]), "r"(a[3]), "r"(b[0]), "r"(b[1]));
}

__device__ __forceinline__ void ldsm_x4(uint32_t* r, uint32_t addr)
{
    asm volatile("ldmatrix.sync.aligned.m8n8.x4.shared.b16 {%0,%1,%2,%3}, [%4];"
        : "=r"(r[0]), "=r"(r[1]), "=r"(r[2]), "=r"(r[3]) : "r"(addr));
}

__device__ __forceinline__ uint32_t smem_u32(const void* p)
{
    uint32_t a;
    asm("{ .reg .u64 t; cvta.to.shared.u64 t, %1; cvt.u32.u64 %0, t; }"
        : "=r"(a) : "l"(p));
    return a;
}
__device__ __forceinline__ void cp_async16(uint32_t dst, const void* src, int src_bytes)
{
    asm volatile("cp.async.cg.shared.global [%0], [%1], 16, %2;"
                 :: "r"(dst), "l"(src), "r"(src_bytes) : "memory");
}
#define CP_COMMIT() asm volatile("cp.async.commit_group;" ::: "memory")
template<int N>
__device__ __forceinline__ void cp_wait()
{
    asm volatile("cp.async.wait_group %0;" :: "n"(N) : "memory");
}

// ---- packed f32x2 helpers ----
__device__ __forceinline__ ull fma_f32x2(ull a, ull b, ull c)
{
    ull d;
    asm("fma.rn.f32x2 %0, %1, %2, %3;" : "=l"(d) : "l"(a), "l"(b), "l"(c));
    return d;
}
__device__ __forceinline__ ull add_f32x2(ull a, ull b)
{
    ull d;
    asm("add.rn.f32x2 %0, %1, %2;" : "=l"(d) : "l"(a), "l"(b));
    return d;
}
__device__ __forceinline__ ull pack_dup(float x)
{
    ull d;
    asm("mov.b64 %0, {%1, %1};" : "=l"(d) : "f"(x));
    return d;
}
__device__ __forceinline__ void unpack2(ull v, float& lo, float& hi)
{
    asm("mov.b64 {%0, %1}, %2;" : "=f"(lo), "=f"(hi) : "l"(v));
}

__device__ __forceinline__ float warp_max_f32(float x)
{
    uint32_t b = __float_as_uint(x);
    uint32_t s = (uint32_t)((int32_t)b >> 31);
    uint32_t key = b ^ (s | 0x80000000u);
    uint32_t m;
    asm("redux.sync.max.u32 %0, %1, 0xffffffff;" : "=r"(m) : "r"(key));
    uint32_t mask = (m & 0x80000000u) ? 0x80000000u : 0xFFFFFFFFu;
    return __uint_as_float(m ^ mask);
}

__device__ __forceinline__ void ld16p(ull* dst, const float* __restrict__ src)
{
    const ulonglong2* p = reinterpret_cast<const ulonglong2*>(src);
    #pragma unroll
    for (int q = 0; q < 8; q++) {
        ulonglong2 v = p[q];
        dst[q * 2]     = v.x;
        dst[q * 2 + 1] = v.y;
    }
}

__device__ __forceinline__ float dot16p(const ull* a, const ull* b)
{
    ull s0 = 0ull, s1 = 0ull, s2 = 0ull, s3 = 0ull;
    #pragma unroll
    for (int j = 0; j < 16; j += 4) {
        s0 = fma_f32x2(a[j],     b[j],     s0);
        s1 = fma_f32x2(a[j + 1], b[j + 1], s1);
        s2 = fma_f32x2(a[j + 2], b[j + 2], s2);
        s3 = fma_f32x2(a[j + 3], b[j + 3], s3);
    }
    ull tt = add_f32x2(add_f32x2(s0, s1), add_f32x2(s2, s3));
    float lo, hi;
    unpack2(tt, lo, hi);
    return lo + hi;
}

// ============================================================
// Kernel 0: weight split
// ============================================================
__global__ void __launch_bounds__(256) split_kernel(
    const float* __restrict__ src, __nv_bfloat16* __restrict__ dst_hi,
    __nv_bfloat16* __restrict__ dst_lo, int n)
{
    int idx = (blockIdx.x * 256 + threadIdx.x) * 8;
    if (idx < n) {
        float4 v0 = *reinterpret_cast<const float4*>(src + idx);
        float4 v1 = *reinterpret_cast<const float4*>(src + idx + 4);
        __nv_bfloat16 h[8], l[8];
        float xs[8] = {v0.x, v0.y, v0.z, v0.w, v1.x, v1.y, v1.z, v1.w};
        #pragma unroll
        for (int q = 0; q < 8; q++) split_bf16(xs[q], h[q], l[q]);
        *reinterpret_cast<uint4*>(dst_hi + idx) = *reinterpret_cast<uint4*>(h);
        *reinterpret_cast<uint4*>(dst_lo + idx) = *reinterpret_cast<uint4*>(l);
    }
}

// ============================================================
// Kernel 1: LayerNorm -> bf16 hi/lo
// ============================================================
__global__ void __launch_bounds__(256) ln_kernel(
    const float* __restrict__ x,
    const float* __restrict__ gamma,
    const float* __restrict__ beta)
{
    int m = blockIdx.x;
    int t = threadIdx.x;
    const float* row = x + (size_t)m * INDIM;
    float v0 = row[t];
    float v1 = row[t + 256];

    float s = v0 + v1;
    #pragma unroll
    for (int o = 16; o; o >>= 1) s += __shfl_xor_sync(0xffffffffu, s, o);

    __shared__ float red[8];
    __shared__ float red2[8];
    int w = t >> 5, lane = t & 31;
    if (lane == 0) red[w] = s;
    __syncthreads();
    float tot = 0.f;
    #pragma unroll
    for (int i = 0; i < 8; i++) tot += red[i];
    float mean = tot * (1.0f / INDIM);

    float d0 = v0 - mean, d1 = v1 - mean;
    float sq = d0 * d0 + d1 * d1;
    #pragma unroll
    for (int o = 16; o; o >>= 1) sq += __shfl_xor_sync(0xffffffffu, sq, o);
    if (lane == 0) red2[w] = sq;
    __syncthreads();
    float vtot = 0.f;
    #pragma unroll
    for (int i = 0; i < 8; i++) vtot += red2[i];
    float inv = rsqrtf(vtot * (1.0f / INDIM) + 1e-5f);

    float r0 = d0 * inv * gamma[t]       + beta[t];
    float r1 = d1 * inv * gamma[t + 256] + beta[t + 256];
    __nv_bfloat16 h0, l0, h1, l1;
    split_bf16(r0, h0, l0);
    split_bf16(r1, h1, l1);
    size_t base = (size_t)m * INDIM;
    g_normed_hi[base + t]       = h0;
    g_normed_lo[base + t]       = l0;
    g_normed_hi[base + t + 256] = h1;
    g_normed_lo[base + t + 256] = l1;
}

// ============================================================
// Kernel 2/5: BF16x3 GEMM (unchanged from R14)
// ============================================================
#define TC_BM 128
#define TC_BN 128
#define TC_BK 16
#define ROWW  12
#define STG_W   (TC_BM * ROWW)
#define STAGE_W (4 * STG_W)
#define NSTAGE  4
#define GEMM_SMEM_BYTES (NSTAGE * STAGE_W * 4)

template<bool RESID>
__global__ void __launch_bounds__(256, 2) mma_gemm_nt(
    const __nv_bfloat16* __restrict__ Ahg, const __nv_bfloat16* __restrict__ Alg,
    const __nv_bfloat16* __restrict__ Bhg, const __nv_bfloat16* __restrict__ Blg,
    float* __restrict__ C,
    const float* __restrict__ resid,
    int Ndim, int Kdim, int m_off)
{
    extern __shared__ uint32_t sm[];

    const int tid    = threadIdx.x;
    const int lane   = tid & 31;
    const int wid    = tid >> 5;
    const int warp_m = wid & 3;
    const int warp_n = wid >> 2;
    const int g      = lane >> 2;
    const int tq     = lane & 3;
    const int mBase  = blockIdx.y * TC_BM + m_off;
    const int nBase  = blockIdx.x * TC_BN;

    const int lrow = tid >> 1;
    const int lce  = (tid & 1) * 8;
    const uint32_t smBase = smem_u32(sm);

    float c[2][8][4];
    #pragma unroll
    for (int am = 0; am < 2; am++)
        #pragma unroll
        for (int an = 0; an < 8; an++)
            #pragma unroll
            for (int q = 0; q < 4; q++) c[am][an][q] = 0.f;

    const int NKB = Kdim / TC_BK;

    const int  nrow  = nBase + lrow;
    const int  nb    = (nrow < Ndim) ? 16 : 0;
    const size_t aRow = (size_t)(mBase + lrow) * Kdim + lce;
    const size_t bRow = (size_t)((nrow < Ndim) ? nrow : 0) * Kdim + lce;
    const uint32_t doff = (uint32_t)(lrow * ROWW * 4 + (tid & 1) * 16);

    auto issue_stage = [&](int kb, int st) {
        const int ko = kb * TC_BK;
        const uint32_t stB = smBase + (uint32_t)(st * STAGE_W) * 4u + doff;
        cp_async16(stB,                                Ahg + aRow + ko, 16);
        cp_async16(stB + (uint32_t)STG_W * 4u,         Alg + aRow + ko, 16);
        cp_async16(stB + (uint32_t)(2 * STG_W) * 4u,   Bhg + bRow + ko, nb);
        cp_async16(stB + (uint32_t)(3 * STG_W) * 4u,   Blg + bRow + ko, nb);
        CP_COMMIT();
    };

    issue_stage(0, 0);
    issue_stage(1, 1);
    issue_stage(2, 2);

    const int mm = lane >> 3;
    const int mr = lane & 7;
    uint32_t offA[2];
    #pragma unroll
    for (int am = 0; am < 2; am++) {
        int mrow = warp_m * 32 + am * 16 + (mm & 1) * 8 + mr;
        offA[am] = (uint32_t)(mrow * ROWW * 4 + (mm >> 1) * 16);
    }
    uint32_t offB[4];
    #pragma unroll
    for (int p = 0; p < 4; p++) {
        int nr = warp_n * 64 + (2 * p + (mm >> 1)) * 8 + mr;
        offB[p] = (uint32_t)(nr * ROWW * 4 + (mm & 1) * 16) + (uint32_t)(2 * STG_W) * 4u;
    }

    for (int kb = 0; kb < NKB; kb++) {
        cp_wait<2>();
        __syncthreads();

        const uint32_t stB = smBase + (uint32_t)((kb & 3) * STAGE_W) * 4u;
        const uint32_t loOff = (uint32_t)STG_W * 4u;

        uint32_t ah[2][4], al[2][4];
        #pragma unroll
        for (int am = 0; am < 2; am++) {
            ldsm_x4(ah[am], stB + offA[am]);
            ldsm_x4(al[am], stB + offA[am] + loOff);
        }
        uint32_t bh[8][2], bl[8][2];
        #pragma unroll
        for (int p = 0; p < 4; p++) {
            uint32_t rh[4], rl[4];
            ldsm_x4(rh, stB + offB[p]);
            ldsm_x4(rl, stB + offB[p] + loOff);
            bh[2 * p][0] = rh[0]; bh[2 * p][1] = rh[1];
            bh[2 * p + 1][0] = rh[2]; bh[2 * p + 1][1] = rh[3];
            bl[2 * p][0] = rl[0]; bl[2 * p][1] = rl[1];
            bl[2 * p + 1][0] = rl[2]; bl[2 * p + 1][1] = rl[3];
        }

        #pragma unroll
        for (int an = 0; an < 8; an++)
            #pragma unroll
            for (int am = 0; am < 2; am++) {
                mma_bf16(c[am][an], ah[am], bh[an]);
                mma_bf16(c[am][an], al[am], bh[an]);
                mma_bf16(c[am][an], ah[am], bl[an]);
            }

        if (kb + 3 < NKB) issue_stage(kb + 3, (kb + 3) & 3);
    }

    #pragma unroll
    for (int am = 0; am < 2; am++) {
        int r0 = mBase + warp_m * 32 + am * 16 + g;
        #pragma unroll
        for (int an = 0; an < 8; an++) {
            int col = nBase + warp_n * 64 + an * 8 + 2 * tq;
            if (col < Ndim) {
                float2 v0 = make_float2(c[am][an][0], c[am][an][1]);
                float2 v1 = make_float2(c[am][an][2], c[am][an][3]);
                if (RESID) {
                    float2 q0 = *reinterpret_cast<const float2*>(
                        resid + (size_t)r0 * Ndim + col);
                    float2 q1 = *reinterpret_cast<const float2*>(
                        resid + (size_t)(r0 + 8) * Ndim + col);
                    v0.x += q0.x; v0.y += q0.y;
                    v1.x += q1.x; v1.y += q1.y;
                }
                *reinterpret_cast<float2*>(C + (size_t)r0 * Ndim + col) = v0;
                *reinterpret_cast<float2*>(C + (size_t)(r0 + 8) * Ndim + col) = v1;
            }
        }
    }
}

// ============================================================
// Kernel 3: per-head activations (chunked via m_off)
// ============================================================
__global__ void __launch_bounds__(256) act_kernel(int m_off)
{
    int m    = blockIdx.x + m_off;
    int wp   = threadIdx.x >> 5;
    int lane = threadIdx.x & 31;
    float* base = g_qkvb + (size_t)m * PROJ + wp * PH;

    const int segs[3] = {0, 64, 192};
    #pragma unroll
    for (int si = 0; si < 3; si++) {
        int seg = segs[si];
        float a  = base[seg + lane];
        float bb = base[seg + 32 + lane];
        float mx = warp_max_f32(fmaxf(a, bb));
        float ea = __expf(a - mx);
        float eb = __expf(bb - mx);
        float s2 = ea + eb;
        #pragma unroll
        for (int o = 16; o; o >>= 1) s2 += __shfl_xor_sync(0xffffffffu, s2, o);
        float inv = 1.0f / s2;
        base[seg + lane]      = ea * inv;
        base[seg + 32 + lane] = eb * inv;
    }
    if (lane < 2) {
        float v = base[320 + lane];
        base[320 + lane] = 1.0f / (1.0f + __expf(-v));
    }
}

// ============================================================
// Kernel 4a: W-scan chunk — input-only delta-rule; emits z_t.
// wbuf layout: [0:64)=q, [64:128)=k, [128:192)=v, [192]=beta
// ============================================================
__global__ void __launch_bounds__(128) wscan_kernel(int s0, int doInit)
{
    int bh = blockIdx.x;
    int b = bh >> 3, h = bh & 7;
    int t = threadIdx.x;
    int i = t >> 1;
    int c = t & 1;

    __shared__ __align__(16) float wbuf[2][196];

    ull W2[16];
    if (doInit) {
        #pragma unroll
        for (int j = 0; j < 16; j++) W2[j] = 0ull;
    } else {
        const ull* ws = g_Wst + ((size_t)bh * 128 + t) * 16;
        #pragma unroll
        for (int j = 0; j < 16; j++) W2[j] = ws[j];
    }

    const float* srcBase = g_qkvb + (size_t)b * PROJ + h * PH;
    const size_t stp = (size_t)BATCH * PROJ;

    {   // preload step s0
        const float* src = srcBase + (size_t)s0 * stp;
        wbuf[0][t] = src[t];
        if (t < 64)  wbuf[0][128 + t] = src[128 + t];
        if (t == 64) wbuf[0][192] = src[320];
    }
    float p0 = 0.f, p1 = 0.f;
    {   // prefetch step s0+1
        const float* src = srcBase + (size_t)(s0 + 1) * stp;
        p0 = src[t];
        if (t < 64)  p1 = src[128 + t];
        if (t == 64) p1 = src[320];
    }
    __syncthreads();

    const int cofs = c * 32;

    for (int ls = 0; ls < CS; ls++) {
        const int s = s0 + ls;
        {
            float* nb = wbuf[(ls + 1) & 1];
            nb[t] = p0;
            if (t < 64)  nb[128 + t] = p1;
            if (t == 64) nb[192] = p1;
        }
        if (s + 2 < S_LEN) {
            const float* src = srcBase + (size_t)(s + 2) * stp;
            p0 = src[t];
            if (t < 64)  p1 = src[128 + t];
            if (t == 64) p1 = src[320];
        }

        const float* in = wbuf[ls & 1];

        ull k2[16];
        ld16p(k2, in + 64 + cofs);
        float vold = dot16p(W2, k2);
        vold += __shfl_xor_sync(0xffffffffu, vold, 1);
        float coef = in[192] * (in[128 + i] - vold);
        ull cd = pack_dup(coef);
        #pragma unroll
        for (int j = 0; j < 16; j++) W2[j] = fma_f32x2(cd, k2[j], W2[j]);

        ull q2[16];
        ld16p(q2, in + cofs);
        float z = dot16p(W2, q2);
        z += __shfl_xor_sync(0xffffffffu, z, 1);

        if (c == 0)
            g_z[(size_t)(s * BATCH + b) * OUTD + h * DHEAD + i] = z;
        __syncthreads();
    }

    ull* ws = g_Wst + ((size_t)bh * 128 + t) * 16;
    #pragma unroll
    for (int j = 0; j < 16; j++) ws[j] = W2[j];
}

// ============================================================
// Kernel 4b: R-scan chunk — serial h chain only.
// rbuf layout: [0:64)=rk, [64:128)=rv, [128]=rbeta
// ============================================================
__global__ void __launch_bounds__(128) rscan_kernel(int s0, int doInit)
{
    int bh = blockIdx.x;
    int b = bh >> 3, h = bh & 7;
    int t    = threadIdx.x;
    int i    = t >> 1;
    int c    = t & 1;
    int lane = t & 31;
    int w    = t >> 5;

    __shared__ __align__(16) float rbuf[2][132];
    __shared__ float z_sh[2][64];
    __shared__ float h_sh[2][64];
    __shared__ __align__(16) float e_sh[4][64];

    ull R2[16];
    if (doInit) {
        #pragma unroll
        for (int j = 0; j < 16; j++) R2[j] = 0ull;
        if (t < 64) h_sh[0][t] = 0.f;
    } else {
        const ull* rs = g_Rst + ((size_t)bh * 128 + t) * 16;
        #pragma unroll
        for (int j = 0; j < 16; j++) R2[j] = rs[j];
        if (t < 64) h_sh[0][t] = g_hst[bh * 64 + t];
    }

    const float* srcBase = g_qkvb + (size_t)b * PROJ + h * PH + 192;
    const float* zBase   = g_z + (size_t)b * OUTD + h * DHEAD;
    const size_t stp  = (size_t)BATCH * PROJ;
    const size_t zstp = (size_t)BATCH * OUTD;

    {   // preload step s0
        const float* src = srcBase + (size_t)s0 * stp;
        rbuf[0][t] = src[t];
        if (t == 0) rbuf[0][128] = src[129];   // src[192+129]=in[321]=rbeta
        if (t < 64) z_sh[0][t] = zBase[(size_t)s0 * zstp + t];
    }
    float p0 = 0.f, p1 = 0.f, pz = 0.f;
    {   // prefetch step s0+1
        const float* src = srcBase + (size_t)(s0 + 1) * stp;
        p0 = src[t];
        if (t == 0) p1 = src[129];
        if (t < 64) pz = zBase[(size_t)(s0 + 1) * zstp + t];
    }
    __syncthreads();

    const int cofs = c * 32;

    for (int ls = 0; ls < CS; ls++) {
        const int s = s0 + ls;
        {
            float* nb = rbuf[(ls + 1) & 1];
            nb[t] = p0;
            if (t == 0) nb[128] = p1;
            if (t < 64) z_sh[(ls + 1) & 1][t] = pz;
        }
        if (s + 2 < S_LEN) {
            const float* src = srcBase + (size_t)(s + 2) * stp;
            p0 = src[t];
            if (t == 0) p1 = src[129];
            if (t < 64) pz = zBase[(size_t)(s + 2) * zstp + t];
        }

        const float* in = rbuf[ls & 1];
        const float* hb = h_sh[ls & 1];

        // softmax(h_prev): redundant per warp
        float h0 = hb[lane];
        float h1 = hb[lane + 32];
        float mx = warp_max_f32(fmaxf(h0, h1));
        float e0 = __expf(h0 - mx);
        float e1 = __expf(h1 - mx);
        e_sh[w][lane]      = e0;
        e_sh[w][lane + 32] = e1;
        float sm = e0 + e1;
        #pragma unroll
        for (int o = 16; o; o >>= 1) sm += __shfl_xor_sync(0xffffffffu, sm, o);
        float invTot = __fdividef(1.0f, sm);
        __syncwarp();

        // R delta-rule update
        ull rk2[16];
        ld16p(rk2, in + cofs);
        float voldR = dot16p(R2, rk2);
        voldR += __shfl_xor_sync(0xffffffffu, voldR, 1);
        float coefR = in[128] * (in[64 + i] - voldR);
        ull crd = pack_dup(coefR);
        #pragma unroll
        for (int j = 0; j < 16; j++) R2[j] = fma_f32x2(crd, rk2[j], R2[j]);

        ull er2[16];
        ld16p(er2, &e_sh[w][cofs]);
        float hd = dot16p(R2, er2);
        hd += __shfl_xor_sync(0xffffffffu, hd, 1);

        if (c == 0) {
            float hn = z_sh[ls & 1][i] + hd * invTot;
            h_sh[(ls + 1) & 1][i] = hn;
            __nv_bfloat16 hi, lo;
            split_bf16(hn, hi, lo);
            size_t idx = (size_t)(s * BATCH + b) * OUTD + h * DHEAD + i;
            g_hs_hi[idx] = hi;
            g_hs_lo[idx] = lo;
        }
        __syncthreads();
    }

    ull* rs = g_Rst + ((size_t)bh * 128 + t) * 16;
    #pragma unroll
    for (int j = 0; j < 16; j++) rs[j] = R2[j];
    if (t < 64) g_hst[bh * 64 + t] = h_sh[0][t];
}

// ============================================================
// Launch: 3-stream chunked pipeline
// ============================================================
extern "C" void kernel_launch(void* const* d_in, const int* in_sizes, int n_in,
                              void* d_out, int out_size)
{
    const float* x      = (const float*)d_in[0];
    const float* W_slow = (const float*)d_in[1];
    const float* W_out  = (const float*)d_in[2];
    const float* gamma  = (const float*)d_in[3];
    const float* betap  = (const float*)d_in[4];
    float* out = (float*)d_out;

    float* p_qkvb = nullptr;
    __nv_bfloat16 *p_nh = nullptr, *p_nl = nullptr, *p_hh = nullptr, *p_hl = nullptr;
    __nv_bfloat16 *p_wsh = nullptr, *p_wsl = nullptr, *p_woh = nullptr, *p_wol = nullptr;
    cudaGetSymbolAddress((void**)&p_qkvb, g_qkvb);
    cudaGetSymbolAddress((void**)&p_nh,   g_normed_hi);
    cudaGetSymbolAddress((void**)&p_nl,   g_normed_lo);
    cudaGetSymbolAddress((void**)&p_hh,   g_hs_hi);
    cudaGetSymbolAddress((void**)&p_hl,   g_hs_lo);
    cudaGetSymbolAddress((void**)&p_wsh,  g_wslow_hi);
    cudaGetSymbolAddress((void**)&p_wsl,  g_wslow_lo);
    cudaGetSymbolAddress((void**)&p_woh,  g_wout_hi);
    cudaGetSymbolAddress((void**)&p_wol,  g_wout_lo);

    static bool init_done = false;
    static cudaStream_t sB, sC;
    static cudaEvent_t evA[NCHUNK], evW[NCHUNK], evR[NCHUNK];
    if (!init_done) {
        cudaFuncSetAttribute((const void*)mma_gemm_nt<false>,
                             cudaFuncAttributeMaxDynamicSharedMemorySize,
                             GEMM_SMEM_BYTES);
        cudaFuncSetAttribute((const void*)mma_gemm_nt<true>,
                             cudaFuncAttributeMaxDynamicSharedMemorySize,
                             GEMM_SMEM_BYTES);
        cudaStreamCreateWithFlags(&sB, cudaStreamNonBlocking);
        cudaStreamCreateWithFlags(&sC, cudaStreamNonBlocking);
        for (int cidx = 0; cidx < NCHUNK; cidx++) {
            cudaEventCreateWithFlags(&evA[cidx], cudaEventDisableTiming);
            cudaEventCreateWithFlags(&evW[cidx], cudaEventDisableTiming);
            cudaEventCreateWithFlags(&evR[cidx], cudaEventDisableTiming);
        }
        init_done = true;
    }

    // 0. weight splits + LayerNorm
    {
        int n1 = PROJ * INDIM;
        split_kernel<<<(n1 / 8 + 255) / 256, 256>>>(W_slow, p_wsh, p_wsl, n1);
        int n2 = INDIM * OUTD;
        split_kernel<<<(n2 / 8 + 255) / 256, 256>>>(W_out, p_woh, p_wol, n2);
    }
    ln_kernel<<<MROWS, 256>>>(x, gamma, betap);

    // 1. GEMM1 + act in chunks (default stream)
    for (int cidx = 0; cidx < NCHUNK; cidx++) {
        dim3 grid((PROJ + TC_BN - 1) / TC_BN, MCHUNK / TC_BM);
        mma_gemm_nt<false><<<grid, 256, GEMM_SMEM_BYTES>>>(
            p_nh, p_nl, p_wsh, p_wsl, p_qkvb, nullptr, PROJ, INDIM,
            cidx * MCHUNK);
        act_kernel<<<MCHUNK, 256>>>(cidx * MCHUNK);
        cudaEventRecord(evA[cidx], 0);
    }

    // 2. W-scan chunks on stream B
    for (int cidx = 0; cidx < NCHUNK; cidx++) {
        cudaStreamWaitEvent(sB, evA[cidx], 0);
        wscan_kernel<<<BATCH * HEADS, 128, 0, sB>>>(cidx * CS, cidx == 0 ? 1 : 0);
        cudaEventRecord(evW[cidx], sB);
    }

    // 3. R-scan chunks on stream C (pipelined one chunk behind wscan)
    for (int cidx = 0; cidx < NCHUNK; cidx++) {
        cudaStreamWaitEvent(sC, evW[cidx], 0);
        rscan_kernel<<<BATCH * HEADS, 128, 0, sC>>>(cidx * CS, cidx == 0 ? 1 : 0);
        cudaEventRecord(evR[cidx], sC);
    }

    // 4. GEMM2 chunks on default stream
    for (int cidx = 0; cidx < NCHUNK; cidx++) {
        cudaStreamWaitEvent(0, evR[cidx], 0);
        dim3 grid(INDIM / TC_BN, MCHUNK / TC_BM);
        mma_gemm_nt<true><<<grid, 256, GEMM_SMEM_BYTES>>>(
            p_hh, p_hl, p_woh, p_wol, out, x, INDIM, OUTD,
            cidx * MCHUNK);
    }
}

// round 17
// speedup vs baseline: 1.1866x; 1.1866x over previous
#include <cuda_runtime.h>
#include <cuda_bf16.h>
#include <cstdint>

#define S_LEN 512
#define BATCH 8
#define HEADS 8
#define DHEAD 64
#define INDIM 512
#define PH    322                 // 5*D + 2
#define PROJ  (HEADS * PH)        // 2576
#define MROWS (S_LEN * BATCH)     // 4096
#define OUTD  (HEADS * DHEAD)     // 512

#define NCHUNK 8
#define CS     (S_LEN / NCHUNK)   // 64 steps per chunk
#define MCHUNK (CS * BATCH)       // 512 rows per chunk

typedef unsigned long long ull;

// ---- scratch (static device memory; no allocation at runtime) ----
__device__ float          g_qkvb[MROWS * PROJ];
__device__ __nv_bfloat16  g_normed_hi[MROWS * INDIM];
__device__ __nv_bfloat16  g_normed_lo[MROWS * INDIM];
__device__ __nv_bfloat16  g_hs_hi[MROWS * OUTD];
__device__ __nv_bfloat16  g_hs_lo[MROWS * OUTD];
__device__ __nv_bfloat16  g_wslow_hi[PROJ * INDIM];
__device__ __nv_bfloat16  g_wslow_lo[PROJ * INDIM];
__device__ __nv_bfloat16  g_wout_hi[INDIM * OUTD];
__device__ __nv_bfloat16  g_wout_lo[INDIM * OUTD];
// scan state across chunks
__device__ ull   g_Wst[64 * 128 * 16];
__device__ ull   g_Rst[64 * 128 * 16];
__device__ float g_hst[64 * 64];

// fp32 -> bf16 hi/lo split
__device__ __forceinline__ void split_bf16(float x, __nv_bfloat16& hi, __nv_bfloat16& lo)
{
    hi = __float2bfloat16_rn(x);
    lo = __float2bfloat16_rn(x - __bfloat162float(hi));
}

// m16n8k16 bf16 tensor-core MMA
__device__ __forceinline__ void mma_bf16(float* c, const uint32_t* a, const uint32_t* b)
{
    asm volatile(
        "mma.sync.aligned.m16n8k16.row.col.f32.bf16.bf16.f32 "
        "{%0,%1,%2,%3}, {%4,%5,%6,%7}, {%8,%9}, {%0,%1,%2,%3};"
        : "+f"(c[0]), "+f"(c[1]), "+f"(c[2]), "+f"(c[3])
        : "r"(a[0]), "r"(a[1]), "r"(a[2]), "r"(a[3]), "r"(b[0]), "r"(b[1]));
}

__device__ __forceinline__ void ldsm_x4(uint32_t* r, uint32_t addr)
{
    asm volatile("ldmatrix.sync.aligned.m8n8.x4.shared.b16 {%0,%1,%2,%3}, [%4];"
        : "=r"(r[0]), "=r"(r[1]), "=r"(r[2]), "=r"(r[3]) : "r"(addr));
}

__device__ __forceinline__ uint32_t smem_u32(const void* p)
{
    uint32_t a;
    asm("{ .reg .u64 t; cvta.to.shared.u64 t, %1; cvt.u32.u64 %0, t; }"
        : "=r"(a) : "l"(p));
    return a;
}
__device__ __forceinline__ void cp_async16(uint32_t dst, const void* src, int src_bytes)
{
    asm volatile("cp.async.cg.shared.global [%0], [%1], 16, %2;"
                 :: "r"(dst), "l"(src), "r"(src_bytes) : "memory");
}
#define CP_COMMIT() asm volatile("cp.async.commit_group;" ::: "memory")
template<int N>
__device__ __forceinline__ void cp_wait()
{
    asm volatile("cp.async.wait_group %0;" :: "n"(N) : "memory");
}

// ---- packed f32x2 helpers (scan) ----
__device__ __forceinline__ ull fma_f32x2(ull a, ull b, ull c)
{
    ull d;
    asm("fma.rn.f32x2 %0, %1, %2, %3;" : "=l"(d) : "l"(a), "l"(b), "l"(c));
    return d;
}
__device__ __forceinline__ ull add_f32x2(ull a, ull b)
{
    ull d;
    asm("add.rn.f32x2 %0, %1, %2;" : "=l"(d) : "l"(a), "l"(b));
    return d;
}
__device__ __forceinline__ ull pack_dup(float x)
{
    ull d;
    asm("mov.b64 %0, {%1, %1};" : "=l"(d) : "f"(x));
    return d;
}
__device__ __forceinline__ void unpack2(ull v, float& lo, float& hi)
{
    asm("mov.b64 {%0, %1}, %2;" : "=f"(lo), "=f"(hi) : "l"(v));
}

__device__ __forceinline__ float warp_max_f32(float x)
{
    uint32_t b = __float_as_uint(x);
    uint32_t s = (uint32_t)((int32_t)b >> 31);
    uint32_t key = b ^ (s | 0x80000000u);
    uint32_t m;
    asm("redux.sync.max.u32 %0, %1, 0xffffffff;" : "=r"(m) : "r"(key));
    uint32_t mask = (m & 0x80000000u) ? 0x80000000u : 0xFFFFFFFFu;
    return __uint_as_float(m ^ mask);
}

// ============================================================
// Kernel 0: weight split
// ============================================================
__global__ void __launch_bounds__(256) split_kernel(
    const float* __restrict__ src, __nv_bfloat16* __restrict__ dst_hi,
    __nv_bfloat16* __restrict__ dst_lo, int n)
{
    int idx = (blockIdx.x * 256 + threadIdx.x) * 8;
    if (idx < n) {
        float4 v0 = *reinterpret_cast<const float4*>(src + idx);
        float4 v1 = *reinterpret_cast<const float4*>(src + idx + 4);
        __nv_bfloat16 h[8], l[8];
        float xs[8] = {v0.x, v0.y, v0.z, v0.w, v1.x, v1.y, v1.z, v1.w};
        #pragma unroll
        for (int q = 0; q < 8; q++) split_bf16(xs[q], h[q], l[q]);
        *reinterpret_cast<uint4*>(dst_hi + idx) = *reinterpret_cast<uint4*>(h);
        *reinterpret_cast<uint4*>(dst_lo + idx) = *reinterpret_cast<uint4*>(l);
    }
}

// ============================================================
// Kernel 1: LayerNorm -> bf16 hi/lo
// ============================================================
__global__ void __launch_bounds__(256) ln_kernel(
    const float* __restrict__ x,
    const float* __restrict__ gamma,
    const float* __restrict__ beta)
{
    int m = blockIdx.x;
    int t = threadIdx.x;
    const float* row = x + (size_t)m * INDIM;
    float v0 = row[t];
    float v1 = row[t + 256];

    float s = v0 + v1;
    #pragma unroll
    for (int o = 16; o; o >>= 1) s += __shfl_xor_sync(0xffffffffu, s, o);

    __shared__ float red[8];
    __shared__ float red2[8];
    int w = t >> 5, lane = t & 31;
    if (lane == 0) red[w] = s;
    __syncthreads();
    float tot = 0.f;
    #pragma unroll
    for (int i = 0; i < 8; i++) tot += red[i];
    float mean = tot * (1.0f / INDIM);

    float d0 = v0 - mean, d1 = v1 - mean;
    float sq = d0 * d0 + d1 * d1;
    #pragma unroll
    for (int o = 16; o; o >>= 1) sq += __shfl_xor_sync(0xffffffffu, sq, o);
    if (lane == 0) red2[w] = sq;
    __syncthreads();
    float vtot = 0.f;
    #pragma unroll
    for (int i = 0; i < 8; i++) vtot += red2[i];
    float inv = rsqrtf(vtot * (1.0f / INDIM) + 1e-5f);

    float r0 = d0 * inv * gamma[t]       + beta[t];
    float r1 = d1 * inv * gamma[t + 256] + beta[t + 256];
    __nv_bfloat16 h0, l0, h1, l1;
    split_bf16(r0, h0, l0);
    split_bf16(r1, h1, l1);
    size_t base = (size_t)m * INDIM;
    g_normed_hi[base + t]       = h0;
    g_normed_lo[base + t]       = l0;
    g_normed_hi[base + t + 256] = h1;
    g_normed_lo[base + t + 256] = l1;
}

// ============================================================
// Kernel 2/5: BF16x3 GEMM, 4-stage cp.async, BK=16, ldmatrix
// ============================================================
#define TC_BM 128
#define TC_BN 128
#define TC_BK 16
#define ROWW  12
#define STG_W   (TC_BM * ROWW)
#define STAGE_W (4 * STG_W)
#define NSTAGE  4
#define GEMM_SMEM_BYTES (NSTAGE * STAGE_W * 4)

template<bool RESID>
__global__ void __launch_bounds__(256, 2) mma_gemm_nt(
    const __nv_bfloat16* __restrict__ Ahg, const __nv_bfloat16* __restrict__ Alg,
    const __nv_bfloat16* __restrict__ Bhg, const __nv_bfloat16* __restrict__ Blg,
    float* __restrict__ C,
    const float* __restrict__ resid,
    int Ndim, int Kdim, int m_off)
{
    extern __shared__ uint32_t sm[];

    const int tid    = threadIdx.x;
    const int lane   = tid & 31;
    const int wid    = tid >> 5;
    const int warp_m = wid & 3;
    const int warp_n = wid >> 2;
    const int g      = lane >> 2;
    const int tq     = lane & 3;
    const int mBase  = blockIdx.y * TC_BM + m_off;
    const int nBase  = blockIdx.x * TC_BN;

    const int lrow = tid >> 1;
    const int lce  = (tid & 1) * 8;
    const uint32_t smBase = smem_u32(sm);

    float c[2][8][4];
    #pragma unroll
    for (int am = 0; am < 2; am++)
        #pragma unroll
        for (int an = 0; an < 8; an++)
            #pragma unroll
            for (int q = 0; q < 4; q++) c[am][an][q] = 0.f;

    const int NKB = Kdim / TC_BK;

    const int  nrow  = nBase + lrow;
    const int  nb    = (nrow < Ndim) ? 16 : 0;
    const size_t aRow = (size_t)(mBase + lrow) * Kdim + lce;
    const size_t bRow = (size_t)((nrow < Ndim) ? nrow : 0) * Kdim + lce;
    const uint32_t doff = (uint32_t)(lrow * ROWW * 4 + (tid & 1) * 16);

    auto issue_stage = [&](int kb, int st) {
        const int ko = kb * TC_BK;
        const uint32_t stB = smBase + (uint32_t)(st * STAGE_W) * 4u + doff;
        cp_async16(stB,                                Ahg + aRow + ko, 16);
        cp_async16(stB + (uint32_t)STG_W * 4u,         Alg + aRow + ko, 16);
        cp_async16(stB + (uint32_t)(2 * STG_W) * 4u,   Bhg + bRow + ko, nb);
        cp_async16(stB + (uint32_t)(3 * STG_W) * 4u,   Blg + bRow + ko, nb);
        CP_COMMIT();
    };

    issue_stage(0, 0);
    issue_stage(1, 1);
    issue_stage(2, 2);

    const int mm = lane >> 3;
    const int mr = lane & 7;
    uint32_t offA[2];
    #pragma unroll
    for (int am = 0; am < 2; am++) {
        int mrow = warp_m * 32 + am * 16 + (mm & 1) * 8 + mr;
        offA[am] = (uint32_t)(mrow * ROWW * 4 + (mm >> 1) * 16);
    }
    uint32_t offB[4];
    #pragma unroll
    for (int p = 0; p < 4; p++) {
        int nr = warp_n * 64 + (2 * p + (mm >> 1)) * 8 + mr;
        offB[p] = (uint32_t)(nr * ROWW * 4 + (mm & 1) * 16) + (uint32_t)(2 * STG_W) * 4u;
    }

    for (int kb = 0; kb < NKB; kb++) {
        cp_wait<2>();
        __syncthreads();

        const uint32_t stB = smBase + (uint32_t)((kb & 3) * STAGE_W) * 4u;
        const uint32_t loOff = (uint32_t)STG_W * 4u;

        uint32_t ah[2][4], al[2][4];
        #pragma unroll
        for (int am = 0; am < 2; am++) {
            ldsm_x4(ah[am], stB + offA[am]);
            ldsm_x4(al[am], stB + offA[am] + loOff);
        }
        uint32_t bh[8][2], bl[8][2];
        #pragma unroll
        for (int p = 0; p < 4; p++) {
            uint32_t rh[4], rl[4];
            ldsm_x4(rh, stB + offB[p]);
            ldsm_x4(rl, stB + offB[p] + loOff);
            bh[2 * p][0] = rh[0]; bh[2 * p][1] = rh[1];
            bh[2 * p + 1][0] = rh[2]; bh[2 * p + 1][1] = rh[3];
            bl[2 * p][0] = rl[0]; bl[2 * p][1] = rl[1];
            bl[2 * p + 1][0] = rl[2]; bl[2 * p + 1][1] = rl[3];
        }

        #pragma unroll
        for (int an = 0; an < 8; an++)
            #pragma unroll
            for (int am = 0; am < 2; am++) {
                mma_bf16(c[am][an], ah[am], bh[an]);
                mma_bf16(c[am][an], al[am], bh[an]);
                mma_bf16(c[am][an], ah[am], bl[an]);
            }

        if (kb + 3 < NKB) issue_stage(kb + 3, (kb + 3) & 3);
    }

    #pragma unroll
    for (int am = 0; am < 2; am++) {
        int r0 = mBase + warp_m * 32 + am * 16 + g;
        #pragma unroll
        for (int an = 0; an < 8; an++) {
            int col = nBase + warp_n * 64 + an * 8 + 2 * tq;
            if (col < Ndim) {
                float2 v0 = make_float2(c[am][an][0], c[am][an][1]);
                float2 v1 = make_float2(c[am][an][2], c[am][an][3]);
                if (RESID) {
                    float2 q0 = *reinterpret_cast<const float2*>(
                        resid + (size_t)r0 * Ndim + col);
                    float2 q1 = *reinterpret_cast<const float2*>(
                        resid + (size_t)(r0 + 8) * Ndim + col);
                    v0.x += q0.x; v0.y += q0.y;
                    v1.x += q1.x; v1.y += q1.y;
                }
                *reinterpret_cast<float2*>(C + (size_t)r0 * Ndim + col) = v0;
                *reinterpret_cast<float2*>(C + (size_t)(r0 + 8) * Ndim + col) = v1;
            }
        }
    }
}

// ============================================================
// Kernel 3: per-head activations (chunked via m_off)
// ============================================================
__global__ void __launch_bounds__(256) act_kernel(int m_off)
{
    int m    = blockIdx.x + m_off;
    int wp   = threadIdx.x >> 5;
    int lane = threadIdx.x & 31;
    float* base = g_qkvb + (size_t)m * PROJ + wp * PH;

    const int segs[3] = {0, 64, 192};
    #pragma unroll
    for (int si = 0; si < 3; si++) {
        int seg = segs[si];
        float a  = base[seg + lane];
        float bb = base[seg + 32 + lane];
        float mx = warp_max_f32(fmaxf(a, bb));
        float ea = __expf(a - mx);
        float eb = __expf(bb - mx);
        float s2 = ea + eb;
        #pragma unroll
        for (int o = 16; o; o >>= 1) s2 += __shfl_xor_sync(0xffffffffu, s2, o);
        float inv = 1.0f / s2;
        base[seg + lane]      = ea * inv;
        base[seg + 32 + lane] = eb * inv;
    }
    if (lane < 2) {
        float v = base[320 + lane];
        base[320 + lane] = 1.0f / (1.0f + __expf(-v));
    }
}

// ============================================================
// Kernel 4: fused scan chunk [s0, s0+CS)
// ============================================================
__device__ __forceinline__ void ld16p(ull* dst, const float* __restrict__ src)
{
    const ulonglong2* p = reinterpret_cast<const ulonglong2*>(src);
    #pragma unroll
    for (int q = 0; q < 8; q++) {
        ulonglong2 v = p[q];
        dst[q * 2]     = v.x;
        dst[q * 2 + 1] = v.y;
    }
}

__device__ __forceinline__ float dot16p(const ull* a, const ull* b)
{
    ull s0 = 0ull, s1 = 0ull, s2 = 0ull, s3 = 0ull;
    #pragma unroll
    for (int j = 0; j < 16; j += 4) {
        s0 = fma_f32x2(a[j],     b[j],     s0);
        s1 = fma_f32x2(a[j + 1], b[j + 1], s1);
        s2 = fma_f32x2(a[j + 2], b[j + 2], s2);
        s3 = fma_f32x2(a[j + 3], b[j + 3], s3);
    }
    ull tt = add_f32x2(add_f32x2(s0, s1), add_f32x2(s2, s3));
    float lo, hi;
    unpack2(tt, lo, hi);
    return lo + hi;
}

#define PHP 324

__global__ void __launch_bounds__(128) scan_kernel(int s0, int doInit)
{
    int bh = blockIdx.x;
    int b = bh >> 3, h = bh & 7;
    int t    = threadIdx.x;
    int i    = t >> 1;
    int c    = t & 1;
    int lane = t & 31;
    int w    = t >> 5;

    __shared__ __align__(16) float buf[2][PHP];
    __shared__ float h_sh[2][64];
    __shared__ __align__(16) float e_sh[4][64];

    ull W2[16], R2[16];
    if (doInit) {
        #pragma unroll
        for (int j = 0; j < 16; j++) { W2[j] = 0ull; R2[j] = 0ull; }
        if (t < 64) h_sh[0][t] = 0.f;
    } else {
        const ull* ws = g_Wst + ((size_t)bh * 128 + t) * 16;
        const ull* rs = g_Rst + ((size_t)bh * 128 + t) * 16;
        #pragma unroll
        for (int j = 0; j < 16; j++) { W2[j] = ws[j]; R2[j] = rs[j]; }
        if (t < 64) h_sh[0][t] = g_hst[bh * 64 + t];
    }

    {
        const float* src = g_qkvb + (size_t)(s0 * BATCH + b) * PROJ + h * PH;
        buf[0][t]       = src[t];
        buf[0][t + 128] = src[t + 128];
        if (t < PH - 256) buf[0][t + 256] = src[t + 256];
    }
    float p0, p1, p2 = 0.f;
    {
        const float* src = g_qkvb + (size_t)((s0 + 1) * BATCH + b) * PROJ + h * PH;
        p0 = src[t];
        p1 = src[t + 128];
        if (t < PH - 256) p2 = src[t + 256];
    }
    __syncthreads();

    const int cofs = c * 32;

    for (int ls = 0; ls < CS; ls++) {
        const int s = s0 + ls;
        {
            float* nb = buf[(ls + 1) & 1];
            nb[t]       = p0;
            nb[t + 128] = p1;
            if (t < PH - 256) nb[t + 256] = p2;
        }
        if (ls + 2 < CS) {
            const float* src = g_qkvb + (size_t)((s + 2) * BATCH + b) * PROJ + h * PH;
            p0 = src[t];
            p1 = src[t + 128];
            if (t < PH - 256) p2 = src[t + 256];
        }

        const float* in = buf[ls & 1];
        const float* hb = h_sh[ls & 1];

        float h0 = hb[lane];
        float h1 = hb[lane + 32];
        float mx = warp_max_f32(fmaxf(h0, h1));
        float e0 = __expf(h0 - mx);
        float e1 = __expf(h1 - mx);
        e_sh[w][lane]      = e0;
        e_sh[w][lane + 32] = e1;
        float sm = e0 + e1;
        #pragma unroll
        for (int o = 16; o; o >>= 1) sm += __shfl_xor_sync(0xffffffffu, sm, o);
        float invTot = __fdividef(1.0f, sm);
        __syncwarp();

        ull k2[16];
        ld16p(k2, in + 64 + cofs);
        float vold = dot16p(W2, k2);
        vold += __shfl_xor_sync(0xffffffffu, vold, 1);
        float coef = in[320] * (in[128 + i] - vold);
        ull cd = pack_dup(coef);
        #pragma unroll
        for (int j = 0; j < 16; j++) W2[j] = fma_f32x2(cd, k2[j], W2[j]);

        ull q2[16];
        ld16p(q2, in + cofs);
        float z = dot16p(W2, q2);
        z += __shfl_xor_sync(0xffffffffu, z, 1);

        ull rk2[16];
        ld16p(rk2, in + 192 + cofs);
        float voldR = dot16p(R2, rk2);
        voldR += __shfl_xor_sync(0xffffffffu, voldR, 1);
        float coefR = in[321] * (in[256 + i] - voldR);
        ull crd = pack_dup(coefR);
        #pragma unroll
        for (int j = 0; j < 16; j++) R2[j] = fma_f32x2(crd, rk2[j], R2[j]);

        ull er2[16];
        ld16p(er2, &e_sh[w][cofs]);
        float hd = dot16p(R2, er2);
        hd += __shfl_xor_sync(0xffffffffu, hd, 1);
        float hn = z + hd * invTot;

        if (c == 0) {
            h_sh[(ls + 1) & 1][i] = hn;
            __nv_bfloat16 hi, lo;
            split_bf16(hn, hi, lo);
            size_t idx = (size_t)(s * BATCH + b) * OUTD + h * DHEAD + i;
            g_hs_hi[idx] = hi;
            g_hs_lo[idx] = lo;
        }
        __syncthreads();
    }

    // persist state (CS even -> final h sits in h_sh[0])
    {
        ull* ws = g_Wst + ((size_t)bh * 128 + t) * 16;
        ull* rs = g_Rst + ((size_t)bh * 128 + t) * 16;
        #pragma unroll
        for (int j = 0; j < 16; j++) { ws[j] = W2[j]; rs[j] = R2[j]; }
        if (t < 64) g_hst[bh * 64 + t] = h_sh[0][t];
    }
}

// ============================================================
// Launch: chunked pipeline; side streams properly forked from
// the capture (origin) stream via a root event.
// ============================================================
extern "C" void kernel_launch(void* const* d_in, const int* in_sizes, int n_in,
                              void* d_out, int out_size)
{
    const float* x      = (const float*)d_in[0];
    const float* W_slow = (const float*)d_in[1];
    const float* W_out  = (const float*)d_in[2];
    const float* gamma  = (const float*)d_in[3];
    const float* betap  = (const float*)d_in[4];
    float* out = (float*)d_out;

    float* p_qkvb = nullptr;
    __nv_bfloat16 *p_nh = nullptr, *p_nl = nullptr, *p_hh = nullptr, *p_hl = nullptr;
    __nv_bfloat16 *p_wsh = nullptr, *p_wsl = nullptr, *p_woh = nullptr, *p_wol = nullptr;
    cudaGetSymbolAddress((void**)&p_qkvb, g_qkvb);
    cudaGetSymbolAddress((void**)&p_nh,   g_normed_hi);
    cudaGetSymbolAddress((void**)&p_nl,   g_normed_lo);
    cudaGetSymbolAddress((void**)&p_hh,   g_hs_hi);
    cudaGetSymbolAddress((void**)&p_hl,   g_hs_lo);
    cudaGetSymbolAddress((void**)&p_wsh,  g_wslow_hi);
    cudaGetSymbolAddress((void**)&p_wsl,  g_wslow_lo);
    cudaGetSymbolAddress((void**)&p_woh,  g_wout_hi);
    cudaGetSymbolAddress((void**)&p_wol,  g_wout_lo);

    static bool init_done = false;
    static cudaStream_t sB, sC;
    static cudaEvent_t evRoot, evA[NCHUNK], evB[NCHUNK], evS, evO, evEnd;
    if (!init_done) {
        cudaFuncSetAttribute((const void*)mma_gemm_nt<false>,
                             cudaFuncAttributeMaxDynamicSharedMemorySize,
                             GEMM_SMEM_BYTES);
        cudaFuncSetAttribute((const void*)mma_gemm_nt<true>,
                             cudaFuncAttributeMaxDynamicSharedMemorySize,
                             GEMM_SMEM_BYTES);
        cudaStreamCreateWithFlags(&sB, cudaStreamNonBlocking);
        cudaStreamCreateWithFlags(&sC, cudaStreamNonBlocking);
        for (int cidx = 0; cidx < NCHUNK; cidx++) {
            cudaEventCreateWithFlags(&evA[cidx], cudaEventDisableTiming);
            cudaEventCreateWithFlags(&evB[cidx], cudaEventDisableTiming);
        }
        cudaEventCreateWithFlags(&evRoot, cudaEventDisableTiming);
        cudaEventCreateWithFlags(&evS, cudaEventDisableTiming);
        cudaEventCreateWithFlags(&evO, cudaEventDisableTiming);
        cudaEventCreateWithFlags(&evEnd, cudaEventDisableTiming);
        init_done = true;
    }

    // fork side streams from the capture (origin) stream
    cudaEventRecord(evRoot, 0);
    cudaStreamWaitEvent(sB, evRoot, 0);
    cudaStreamWaitEvent(sC, evRoot, 0);

    // 0. W_slow split on stream B; W_out split on stream C (concurrent with LN)
    {
        int n1 = PROJ * INDIM;
        split_kernel<<<(n1 / 8 + 255) / 256, 256, 0, sB>>>(W_slow, p_wsh, p_wsl, n1);
        cudaEventRecord(evS, sB);
        int n2 = INDIM * OUTD;
        split_kernel<<<(n2 / 8 + 255) / 256, 256, 0, sC>>>(W_out, p_woh, p_wol, n2);
        cudaEventRecord(evO, sC);
    }

    // 1. LayerNorm on default stream
    ln_kernel<<<MROWS, 256>>>(x, gamma, betap);
    cudaStreamWaitEvent(0, evS, 0);

    // 2. GEMM1 + act in chunks (default stream)
    for (int cidx = 0; cidx < NCHUNK; cidx++) {
        dim3 grid((PROJ + TC_BN - 1) / TC_BN, MCHUNK / TC_BM);
        mma_gemm_nt<false><<<grid, 256, GEMM_SMEM_BYTES>>>(
            p_nh, p_nl, p_wsh, p_wsl, p_qkvb, nullptr, PROJ, INDIM,
            cidx * MCHUNK);
        act_kernel<<<MCHUNK, 256>>>(cidx * MCHUNK);
        cudaEventRecord(evA[cidx], 0);
    }

    // 3. scan chunks on stream B
    for (int cidx = 0; cidx < NCHUNK; cidx++) {
        cudaStreamWaitEvent(sB, evA[cidx], 0);
        scan_kernel<<<BATCH * HEADS, 128, 0, sB>>>(cidx * CS, cidx == 0 ? 1 : 0);
        cudaEventRecord(evB[cidx], sB);
    }

    // 4. GEMM2 chunks on stream C (gated on scan chunk + W_out split)
    for (int cidx = 0; cidx < NCHUNK; cidx++) {
        cudaStreamWaitEvent(sC, evB[cidx], 0);
        dim3 grid(INDIM / TC_BN, MCHUNK / TC_BM);
        mma_gemm_nt<true><<<grid, 256, GEMM_SMEM_BYTES, sC>>>(
            p_hh, p_hl, p_woh, p_wol, out, x, INDIM, OUTD,
            cidx * MCHUNK);
    }

    // join both side streams back into the origin stream
    cudaEventRecord(evEnd, sC);
    cudaStreamWaitEvent(0, evEnd, 0);
    cudaEventRecord(evRoot, sB);
    cudaStreamWaitEvent(0, evRoot, 0);
}